// round 7
// baseline (speedup 1.0000x reference)
#include <cuda_runtime.h>
#include <cstdint>
#include <math.h>

#define Bc   8
#define Nc   1024
#define OBSc 64
#define HIDc 192
#define Hc   3
#define Dc   64
#define BHc  (Bc*Hc)

#define LDA 36
#define LDB 72
#define NTILE (Nc / 32)

// Scratch (device globals; no allocation allowed)
__device__ float g_Wh[BHc * Nc * Dc];     // (bh, n, d), values pre-rounded to tf32
__device__ float g_x [Bc * Nc * HIDc];    // inter-layer activations (full f32)
__device__ float g_si[BHc * Nc];
__device__ float g_sj[BHc * Nc];
__device__ uint32_t g_adjbits[Nc * 32];   // adjacency bitmask, word w of row i

__device__ __forceinline__ uint32_t tf32u(float x){   // round-to-nearest tf32
    uint32_t u; asm("cvt.rna.tf32.f32 %0, %1;" : "=r"(u) : "f"(x));
    return u;
}
__device__ __forceinline__ void mma8(float* d, uint32_t a0, uint32_t a1, uint32_t a2, uint32_t a3,
                                     uint32_t b0, uint32_t b1){
    asm volatile("mma.sync.aligned.m16n8k8.row.col.f32.tf32.tf32.f32 "
        "{%0,%1,%2,%3}, {%4,%5,%6,%7}, {%8,%9}, {%0,%1,%2,%3};"
        : "+f"(d[0]), "+f"(d[1]), "+f"(d[2]), "+f"(d[3])
        : "r"(a0), "r"(a1), "r"(a2), "r"(a3), "r"(b0), "r"(b1));
}

// ---------------------------------------------------------------------------
// Adjacency bitmask: bit l of word (i*32+w) = (adj[i][w*32+l] > 0)
// ---------------------------------------------------------------------------
__global__ __launch_bounds__(256) void adjbits_kernel(const float* __restrict__ adj)
{
    int w = (blockIdx.x * blockDim.x + threadIdx.x) >> 5;
    int lane = threadIdx.x & 31;
    if (w < Nc * 32){
        float v = adj[(size_t)w * 32 + lane];
        uint32_t m = __ballot_sync(0xffffffffu, v > 0.f);
        if (lane == 0) g_adjbits[w] = m;
    }
}

// ---------------------------------------------------------------------------
// Projection (tf32 mma): Wh = X @ W[h]; fused epilogue emits s_i, s_j.
// 128 threads, 64-row tiles, grid (128, 3) = 384 CTAs. Reg-prefetch t+1.
// Wh is stored pre-rounded to tf32 (s_i/s_j use full-precision acc first).
// ---------------------------------------------------------------------------
template<int K, bool FROM_GX>
__global__ __launch_bounds__(128) void proj_mma(const float* __restrict__ Xe,
                                                const float* __restrict__ W,
                                                const float* __restrict__ av)
{
    __shared__ uint32_t As[64 * LDA];
    __shared__ uint32_t Bs[32 * LDB];
    __shared__ float sa[128];

    int tid = threadIdx.x, lane = tid & 31, wid = tid >> 5;
    int g = lane >> 2, tig = lane & 3, wr0 = wid * 16;
    int row0 = blockIdx.x * 64, h = blockIdx.y;
    const float* X = FROM_GX ? (const float*)g_x : Xe;

    sa[tid] = av[h * 128 + tid];

    int ar = tid >> 1, ac = (tid & 1) * 16;   // A loader: row ar, 16 k
    int bk = tid >> 2, bd = (tid & 3) * 16;   // B loader: k row bk, 16 d

    float4 xa[4], wb[4];
    {
        const float* xp = &X[(size_t)(row0 + ar) * K + ac];
        #pragma unroll
        for (int q = 0; q < 4; q++) xa[q] = *(const float4*)&xp[q * 4];
        const float* wp = &W[(size_t)(h * K + bk) * Dc + bd];
        #pragma unroll
        for (int q = 0; q < 4; q++) wb[q] = *(const float4*)&wp[q * 4];
    }

    float acc[8][4] = {};

    constexpr int NT = K / 32;
    for (int t = 0; t < NT; t++){
        {
            const float* xf = (const float*)xa;
            #pragma unroll
            for (int e = 0; e < 16; e++) As[ar * LDA + ac + e] = tf32u(xf[e]);
            const float* wf = (const float*)wb;
            #pragma unroll
            for (int e = 0; e < 16; e++) Bs[bk * LDB + bd + e] = tf32u(wf[e]);
        }
        __syncthreads();
        if (t + 1 < NT){
            const float* xp = &X[(size_t)(row0 + ar) * K + (t + 1) * 32 + ac];
            #pragma unroll
            for (int q = 0; q < 4; q++) xa[q] = *(const float4*)&xp[q * 4];
            const float* wp = &W[(size_t)(h * K + (t + 1) * 32 + bk) * Dc + bd];
            #pragma unroll
            for (int q = 0; q < 4; q++) wb[q] = *(const float4*)&wp[q * 4];
        }
        #pragma unroll
        for (int ks = 0; ks < 4; ks++){
            int ka = ks * 8 + tig;
            uint32_t a0 = As[(wr0 + g    ) * LDA + ka    ];
            uint32_t a1 = As[(wr0 + g + 8) * LDA + ka    ];
            uint32_t a2 = As[(wr0 + g    ) * LDA + ka + 4];
            uint32_t a3 = As[(wr0 + g + 8) * LDA + ka + 4];
            #pragma unroll
            for (int nt = 0; nt < 8; nt++){
                uint32_t b0 = Bs[ ka      * LDB + nt * 8 + g];
                uint32_t b1 = Bs[(ka + 4) * LDB + nt * 8 + g];
                mma8(acc[nt], a0, a1, a2, a3, b0, b1);
            }
        }
        __syncthreads();
    }

    // Epilogue: s_i/s_j from full-precision fragments, then tf32 Wh store.
    float si0 = 0.f, sj0 = 0.f, si1 = 0.f, sj1 = 0.f;
    #pragma unroll
    for (int nt = 0; nt < 8; nt++){
        #pragma unroll
        for (int c = 0; c < 2; c++){
            int col = nt * 8 + 2 * tig + c;
            float al = sa[col], ar2 = sa[64 + col];
            si0 += acc[nt][c] * al;      sj0 += acc[nt][c] * ar2;
            si1 += acc[nt][2 + c] * al;  sj1 += acc[nt][2 + c] * ar2;
        }
    }
    si0 += __shfl_xor_sync(0xffffffffu, si0, 1); si0 += __shfl_xor_sync(0xffffffffu, si0, 2);
    sj0 += __shfl_xor_sync(0xffffffffu, sj0, 1); sj0 += __shfl_xor_sync(0xffffffffu, sj0, 2);
    si1 += __shfl_xor_sync(0xffffffffu, si1, 1); si1 += __shfl_xor_sync(0xffffffffu, si1, 2);
    sj1 += __shfl_xor_sync(0xffffffffu, sj1, 1); sj1 += __shfl_xor_sync(0xffffffffu, sj1, 2);

    int r = row0 + wr0 + g;
    int b = r >> 10, n = r & (Nc - 1);
    int bh = b * Hc + h;
    if (tig == 0){
        g_si[(size_t)bh * Nc + n] = si0;     g_sj[(size_t)bh * Nc + n] = sj0;
        g_si[(size_t)bh * Nc + n + 8] = si1; g_sj[(size_t)bh * Nc + n + 8] = sj1;
    }
    float* wh0 = &g_Wh[((size_t)bh * Nc + n    ) * Dc];
    float* wh1 = &g_Wh[((size_t)bh * Nc + n + 8) * Dc];
    #pragma unroll
    for (int nt = 0; nt < 8; nt++){
        *(float2*)&wh0[nt * 8 + 2 * tig] =
            make_float2(__uint_as_float(tf32u(acc[nt][0])), __uint_as_float(tf32u(acc[nt][1])));
        *(float2*)&wh1[nt * 8 + 2 * tig] =
            make_float2(__uint_as_float(tf32u(acc[nt][2])), __uint_as_float(tf32u(acc[nt][3])));
    }
}

// ---------------------------------------------------------------------------
// Attention: 128 threads, 64-row tiles, grid (16, 24) = 384 CTAs.
// P A-fragments computed in registers; Wh staged (already tf32) in XOR
// fragment layout; adjacency via bitmask.
// ---------------------------------------------------------------------------
template<bool ELU, bool TO_GX>
__global__ __launch_bounds__(128) void attn_frag(float* __restrict__ out_ext)
{
    __shared__ __align__(16) float4 jtab[Nc];            // (s_j, e^{s_j}, e^{0.2 s_j}, -)
    __shared__ float sil[64], A1v[64], A2v[64], den[64], red[4];
    __shared__ __align__(16) uint32_t wsf[2][32 * 64];

    int tid = threadIdx.x, lane = tid & 31, wid = tid >> 5;
    int g = lane >> 2, tig = lane & 3, wr0 = wid * 16;
    int r0 = wr0 + g, r1 = r0 + 8;
    int bh = blockIdx.y, i0 = blockIdx.x * 64;

    const float* sjg = &g_sj[(size_t)bh * Nc];
    const float* sig = &g_si[(size_t)bh * Nc];

    // ---- Prologue ----
    float lmax = -3.0e38f;
    for (int j = tid; j < Nc; j += 128){ float v = sjg[j]; jtab[j].x = v; lmax = fmaxf(lmax, v); }
    #pragma unroll
    for (int o = 16; o; o >>= 1) lmax = fmaxf(lmax, __shfl_xor_sync(0xffffffffu, lmax, o));
    if (lane == 0) red[wid] = lmax;
    __syncthreads();
    float smax = fmaxf(fmaxf(red[0], red[1]), fmaxf(red[2], red[3]));
    for (int j = tid; j < Nc; j += 128){
        float v = jtab[j].x;
        jtab[j].y = expf(v); jtab[j].z = expf(0.2f * v);
    }
    if (tid < 64){
        float s = sig[i0 + tid]; sil[tid] = s;
        float e = s + smax; float m = e > 0.f ? e : 0.2f * e;   // exact row-max bound
        A1v[tid] = expf(s - m); A2v[tid] = expf(0.2f * s - m);
    }
    __syncthreads();

    float psil0 = sil[r0], pa10 = A1v[r0], pa20 = A2v[r0];
    float psil1 = sil[r1], pa11 = A1v[r1], pa21 = A2v[r1];
    const uint32_t* bits0 = &g_adjbits[(size_t)(i0 + r0) * 32];
    const uint32_t* bits1 = &g_adjbits[(size_t)(i0 + r1) * 32];

    // Staging: thread covers row sk = tid>>2, 16 cols starting at (tid&3)*16.
    int sk = tid >> 2, sq = tid & 3;
    const float* wsrc = &g_Wh[((size_t)bh * Nc + sk) * Dc + sq * 16];
    int slot_w0 = (sk & 3) << 1;

    float acc[8][4] = {};
    float d0 = 0.f, d1 = 0.f;

    float4 wc[4], wn[4];

    // Pipeline prologue: stage tile 0, prefetch tile 1.
    {
        #pragma unroll
        for (int q = 0; q < 4; q++) wc[q] = *(const float4*)&wsrc[q * 4];
        const float* vf = (const float*)wc;
        #pragma unroll
        for (int e = 0; e < 16; e++){
            int gc = e & 7, snt = sq * 2 + (e >> 3);
            wsf[0][sk * 64 + ((gc ^ slot_w0) << 3) + snt] = __float_as_uint(vf[e]);
        }
    }
    #pragma unroll
    for (int q = 0; q < 4; q++) wc[q] = *(const float4*)&wsrc[(size_t)32 * Dc + q * 4];
    uint32_t wA_c = bits0[0], wB_c = bits1[0];
    uint32_t wA_n = bits0[1], wB_n = bits1[1];
    __syncthreads();

    for (int t = 0; t < NTILE; t++){
        uint32_t wA2 = 0, wB2 = 0;
        if (t + 2 < NTILE){
            #pragma unroll
            for (int q = 0; q < 4; q++) wn[q] = *(const float4*)&wsrc[(size_t)(t + 2) * 32 * Dc + q * 4];
            wA2 = bits0[t + 2]; wB2 = bits1[t + 2];
        }
        if (t + 1 < NTILE){
            const float* vf = (const float*)wc;
            uint32_t* W = wsf[(t + 1) & 1];
            #pragma unroll
            for (int e = 0; e < 16; e++){
                int gc = e & 7, snt = sq * 2 + (e >> 3);
                W[sk * 64 + ((gc ^ slot_w0) << 3) + snt] = __float_as_uint(vf[e]);
            }
        }
        // ---- compute tile t ----
        const uint32_t* W = wsf[t & 1];
        int slot_r = g ^ (tig << 1);
        #pragma unroll
        for (int ks = 0; ks < 4; ks++){
            int jb = t * 32 + ks * 8;
            float4 t0 = jtab[jb + tig];
            float4 t1 = jtab[jb + tig + 4];
            int sh = ks * 8 + tig;
            float p0 = (psil0 + t0.x > 0.f) ? pa10 * t0.y : pa20 * t0.z; if (!((wA_c >> sh) & 1))       p0 = 0.f;
            float p1 = (psil1 + t0.x > 0.f) ? pa11 * t0.y : pa21 * t0.z; if (!((wB_c >> sh) & 1))       p1 = 0.f;
            float p2 = (psil0 + t1.x > 0.f) ? pa10 * t1.y : pa20 * t1.z; if (!((wA_c >> (sh + 4)) & 1)) p2 = 0.f;
            float p3 = (psil1 + t1.x > 0.f) ? pa11 * t1.y : pa21 * t1.z; if (!((wB_c >> (sh + 4)) & 1)) p3 = 0.f;
            uint32_t a0 = tf32u(p0), a1 = tf32u(p1), a2 = tf32u(p2), a3 = tf32u(p3);
            d0 += __uint_as_float(a0) + __uint_as_float(a2);
            d1 += __uint_as_float(a1) + __uint_as_float(a3);
            const uint32_t* br0 = &W[ sh      * 64 + slot_r * 8];
            const uint32_t* br1 = &W[(sh + 4) * 64 + slot_r * 8];
            uint4 b00 = *(const uint4*)br0;
            uint4 b01 = *(const uint4*)(br0 + 4);
            uint4 b10 = *(const uint4*)br1;
            uint4 b11 = *(const uint4*)(br1 + 4);
            mma8(acc[0], a0, a1, a2, a3, b00.x, b10.x);
            mma8(acc[1], a0, a1, a2, a3, b00.y, b10.y);
            mma8(acc[2], a0, a1, a2, a3, b00.z, b10.z);
            mma8(acc[3], a0, a1, a2, a3, b00.w, b10.w);
            mma8(acc[4], a0, a1, a2, a3, b01.x, b11.x);
            mma8(acc[5], a0, a1, a2, a3, b01.y, b11.y);
            mma8(acc[6], a0, a1, a2, a3, b01.z, b11.z);
            mma8(acc[7], a0, a1, a2, a3, b01.w, b11.w);
        }
        #pragma unroll
        for (int q = 0; q < 4; q++) wc[q] = wn[q];
        wA_c = wA_n; wB_c = wB_n; wA_n = wA2; wB_n = wB2;
        __syncthreads();
    }

    // Denominator: reduce over tig (xor 1, 2).
    d0 += __shfl_xor_sync(0xffffffffu, d0, 1); d0 += __shfl_xor_sync(0xffffffffu, d0, 2);
    d1 += __shfl_xor_sync(0xffffffffu, d1, 1); d1 += __shfl_xor_sync(0xffffffffu, d1, 2);
    if (tig == 0){ den[r0] = d0; den[r1] = d1; }
    __syncthreads();

    // Epilogue: normalize (+ELU), write concat layout.
    float inv0 = 1.f / den[r0];
    float inv1 = 1.f / den[r1];
    int b = bh / Hc, hh = bh % Hc;
    float* op = TO_GX ? (float*)g_x : out_ext;
    int n = i0 + r0;
    float* o0 = &op[(size_t)(b * Nc + n    ) * HIDc + hh * Dc];
    float* o1 = &op[(size_t)(b * Nc + n + 8) * HIDc + hh * Dc];
    #pragma unroll
    for (int nt = 0; nt < 8; nt++){
        float v00 = acc[nt][0] * inv0, v01 = acc[nt][1] * inv0;
        float v10 = acc[nt][2] * inv1, v11 = acc[nt][3] * inv1;
        if (ELU){
            v00 = v00 > 0.f ? v00 : expm1f(v00);
            v01 = v01 > 0.f ? v01 : expm1f(v01);
            v10 = v10 > 0.f ? v10 : expm1f(v10);
            v11 = v11 > 0.f ? v11 : expm1f(v11);
        }
        *(float2*)&o0[nt * 8 + 2 * tig] = make_float2(v00, v01);
        *(float2*)&o1[nt * 8 + 2 * tig] = make_float2(v10, v11);
    }
}

// ---------------------------------------------------------------------------
extern "C" void kernel_launch(void* const* d_in, const int* in_sizes, int n_in,
                              void* d_out, int out_size)
{
    const float* h   = (const float*)d_in[0];
    const float* adj = (const float*)d_in[1];
    const float* W1  = (const float*)d_in[2];
    const float* a1  = (const float*)d_in[3];
    const float* W2  = (const float*)d_in[4];
    const float* a2  = (const float*)d_in[5];
    float* out = (float*)d_out;

    dim3 projGrid(Bc * Nc / 64, Hc);    // (128, 3) = 384
    dim3 attnGrid(Nc / 64, BHc);        // (16, 24) = 384

    adjbits_kernel<<<(Nc * 32 * 32) / 256, 256>>>(adj);
    proj_mma<OBSc, false><<<projGrid, 128>>>(h, W1, a1);
    attn_frag<true,  true ><<<attnGrid, 128>>>(nullptr);
    proj_mma<HIDc, true ><<<projGrid, 128>>>(nullptr, W2, a2);
    attn_frag<false, false><<<attnGrid, 128>>>(out);
}

// round 8
// speedup vs baseline: 1.7581x; 1.7581x over previous
#include <cuda_runtime.h>
#include <cstdint>
#include <math.h>

#define Bc   8
#define Nc   1024
#define OBSc 64
#define HIDc 192
#define Hc   3
#define Dc   64
#define BHc  (Bc*Hc)

#define LDA 36
#define LDB 72
#define JSPLIT 2
#define NTILE_H (Nc / 32 / JSPLIT)   // 16 tiles per j-half

// Scratch (device globals; no allocation allowed)
__device__ float g_Wh[BHc * Nc * Dc];             // (bh, n, d), pre-rounded tf32
__device__ float g_x [Bc * Nc * HIDc];            // inter-layer activations
__device__ float g_si[BHc * Nc];
__device__ float g_sj[BHc * Nc];
__device__ uint32_t g_adjbits[Nc * 32];           // adjacency bitmask
__device__ float g_part[JSPLIT][BHc * Nc * Dc];   // unnormalized partial O
__device__ float g_pden[JSPLIT][BHc * Nc];        // partial denominators

__device__ __forceinline__ uint32_t tf32u(float x){
    uint32_t u; asm("cvt.rna.tf32.f32 %0, %1;" : "=r"(u) : "f"(x));
    return u;
}
__device__ __forceinline__ void mma8(float* d, uint32_t a0, uint32_t a1, uint32_t a2, uint32_t a3,
                                     uint32_t b0, uint32_t b1){
    asm volatile("mma.sync.aligned.m16n8k8.row.col.f32.tf32.tf32.f32 "
        "{%0,%1,%2,%3}, {%4,%5,%6,%7}, {%8,%9}, {%0,%1,%2,%3};"
        : "+f"(d[0]), "+f"(d[1]), "+f"(d[2]), "+f"(d[3])
        : "r"(a0), "r"(a1), "r"(a2), "r"(a3), "r"(b0), "r"(b1));
}

// ---------------------------------------------------------------------------
__global__ __launch_bounds__(256) void adjbits_kernel(const float* __restrict__ adj)
{
    int w = (blockIdx.x * blockDim.x + threadIdx.x) >> 5;
    int lane = threadIdx.x & 31;
    if (w < Nc * 32){
        float v = adj[(size_t)w * 32 + lane];
        uint32_t m = __ballot_sync(0xffffffffu, v > 0.f);
        if (lane == 0) g_adjbits[w] = m;
    }
}

// ---------------------------------------------------------------------------
// Projection (tf32 mma): Wh = X @ W[h]; fused epilogue emits s_i, s_j.
// 256 threads, 128-row tiles (R6 shape — proven).
// ---------------------------------------------------------------------------
template<int K, bool FROM_GX>
__global__ __launch_bounds__(256) void proj_mma(const float* __restrict__ Xe,
                                                const float* __restrict__ W,
                                                const float* __restrict__ av)
{
    __shared__ uint32_t As[128 * LDA];
    __shared__ uint32_t Bs[32 * LDB];
    __shared__ float sa[128];

    int tid = threadIdx.x, lane = tid & 31, wid = tid >> 5;
    int g = lane >> 2, tig = lane & 3, wr0 = wid * 16;
    int row0 = blockIdx.x * 128, h = blockIdx.y;
    const float* X = FROM_GX ? (const float*)g_x : Xe;

    if (tid < 128) sa[tid] = av[h * 128 + tid];

    int ar = tid >> 1, ac = (tid & 1) * 16;
    int bk = tid >> 3, bd = (tid & 7) * 8;

    float acc[8][4] = {};

    #pragma unroll 2
    for (int t = 0; t < K / 32; t++){
        __syncthreads();
        {
            const float* xp = &X[(size_t)(row0 + ar) * K + t * 32 + ac];
            #pragma unroll
            for (int q = 0; q < 4; q++){
                float4 v = *(const float4*)&xp[q * 4];
                As[ar * LDA + ac + q * 4 + 0] = tf32u(v.x);
                As[ar * LDA + ac + q * 4 + 1] = tf32u(v.y);
                As[ar * LDA + ac + q * 4 + 2] = tf32u(v.z);
                As[ar * LDA + ac + q * 4 + 3] = tf32u(v.w);
            }
            const float* wp = &W[(size_t)(h * K + t * 32 + bk) * Dc + bd];
            float4 w0 = *(const float4*)&wp[0];
            float4 w1 = *(const float4*)&wp[4];
            Bs[bk * LDB + bd + 0] = tf32u(w0.x); Bs[bk * LDB + bd + 1] = tf32u(w0.y);
            Bs[bk * LDB + bd + 2] = tf32u(w0.z); Bs[bk * LDB + bd + 3] = tf32u(w0.w);
            Bs[bk * LDB + bd + 4] = tf32u(w1.x); Bs[bk * LDB + bd + 5] = tf32u(w1.y);
            Bs[bk * LDB + bd + 6] = tf32u(w1.z); Bs[bk * LDB + bd + 7] = tf32u(w1.w);
        }
        __syncthreads();
        #pragma unroll
        for (int ks = 0; ks < 4; ks++){
            int ka = ks * 8 + tig;
            uint32_t a0 = As[(wr0 + g    ) * LDA + ka    ];
            uint32_t a1 = As[(wr0 + g + 8) * LDA + ka    ];
            uint32_t a2 = As[(wr0 + g    ) * LDA + ka + 4];
            uint32_t a3 = As[(wr0 + g + 8) * LDA + ka + 4];
            #pragma unroll
            for (int nt = 0; nt < 8; nt++){
                uint32_t b0 = Bs[ ka      * LDB + nt * 8 + g];
                uint32_t b1 = Bs[(ka + 4) * LDB + nt * 8 + g];
                mma8(acc[nt], a0, a1, a2, a3, b0, b1);
            }
        }
    }

    float si0 = 0.f, sj0 = 0.f, si1 = 0.f, sj1 = 0.f;
    #pragma unroll
    for (int nt = 0; nt < 8; nt++){
        #pragma unroll
        for (int c = 0; c < 2; c++){
            int col = nt * 8 + 2 * tig + c;
            float al = sa[col], ar2 = sa[64 + col];
            si0 += acc[nt][c] * al;      sj0 += acc[nt][c] * ar2;
            si1 += acc[nt][2 + c] * al;  sj1 += acc[nt][2 + c] * ar2;
        }
    }
    si0 += __shfl_xor_sync(0xffffffffu, si0, 1); si0 += __shfl_xor_sync(0xffffffffu, si0, 2);
    sj0 += __shfl_xor_sync(0xffffffffu, sj0, 1); sj0 += __shfl_xor_sync(0xffffffffu, sj0, 2);
    si1 += __shfl_xor_sync(0xffffffffu, si1, 1); si1 += __shfl_xor_sync(0xffffffffu, si1, 2);
    sj1 += __shfl_xor_sync(0xffffffffu, sj1, 1); sj1 += __shfl_xor_sync(0xffffffffu, sj1, 2);

    int r = row0 + wr0 + g;
    int b = r >> 10, n = r & (Nc - 1);
    int bh = b * Hc + h;
    if (tig == 0){
        g_si[(size_t)bh * Nc + n] = si0;     g_sj[(size_t)bh * Nc + n] = sj0;
        g_si[(size_t)bh * Nc + n + 8] = si1; g_sj[(size_t)bh * Nc + n + 8] = sj1;
    }
    float* wh0 = &g_Wh[((size_t)bh * Nc + n    ) * Dc];
    float* wh1 = &g_Wh[((size_t)bh * Nc + n + 8) * Dc];
    #pragma unroll
    for (int nt = 0; nt < 8; nt++){
        *(float2*)&wh0[nt * 8 + 2 * tig] =
            make_float2(__uint_as_float(tf32u(acc[nt][0])), __uint_as_float(tf32u(acc[nt][1])));
        *(float2*)&wh1[nt * 8 + 2 * tig] =
            make_float2(__uint_as_float(tf32u(acc[nt][2])), __uint_as_float(tf32u(acc[nt][3])));
    }
}

// ---------------------------------------------------------------------------
// Attention partial: 256 threads, 128-row tiles, j-half per blockIdx.z.
// Writes unnormalized partial O (bh,n,d) + partial den. Grid (8, 24, 2).
// ---------------------------------------------------------------------------
__global__ __launch_bounds__(256) void attn_frag(void)
{
    __shared__ __align__(16) float4 jtab[Nc / JSPLIT];   // (s_j, e^{s_j}, e^{0.2 s_j}, -)
    __shared__ float sil[128], A1v[128], A2v[128], red[8];
    __shared__ __align__(16) uint32_t wsf[2][32 * 64];

    int tid = threadIdx.x, lane = tid & 31, wid = tid >> 5;
    int g = lane >> 2, tig = lane & 3, wr0 = wid * 16;
    int r0 = wr0 + g, r1 = r0 + 8;
    int bh = blockIdx.y, i0 = blockIdx.x * 128;
    int jh = blockIdx.z, jbase = jh * (Nc / JSPLIT);

    const float* sjg = &g_sj[(size_t)bh * Nc];
    const float* sig = &g_si[(size_t)bh * Nc];

    // ---- Prologue: global max over ALL j (shared scale), tables for own half ----
    float lmax = -3.0e38f;
    for (int j = tid; j < Nc; j += 256) lmax = fmaxf(lmax, sjg[j]);
    #pragma unroll
    for (int o = 16; o; o >>= 1) lmax = fmaxf(lmax, __shfl_xor_sync(0xffffffffu, lmax, o));
    if (lane == 0) red[wid] = lmax;
    __syncthreads();
    float smax = red[0];
    #pragma unroll
    for (int w2 = 1; w2 < 8; w2++) smax = fmaxf(smax, red[w2]);
    for (int j = tid; j < Nc / JSPLIT; j += 256){
        float v = sjg[jbase + j];
        jtab[j].x = v; jtab[j].y = expf(v); jtab[j].z = expf(0.2f * v);
    }
    if (tid < 128){
        float s = sig[i0 + tid]; sil[tid] = s;
        float e = s + smax; float m = e > 0.f ? e : 0.2f * e;   // exact row-max bound
        A1v[tid] = expf(s - m); A2v[tid] = expf(0.2f * s - m);
    }
    __syncthreads();

    float psil0 = sil[r0], pa10 = A1v[r0], pa20 = A2v[r0];
    float psil1 = sil[r1], pa11 = A1v[r1], pa21 = A2v[r1];
    const uint32_t* bits0 = &g_adjbits[(size_t)(i0 + r0) * 32 + jh * NTILE_H];
    const uint32_t* bits1 = &g_adjbits[(size_t)(i0 + r1) * 32 + jh * NTILE_H];

    // Wh staging: thread (sk = tid>>3, snt = tid&7): row j, 8 cols.
    int sk = tid >> 3, snt = tid & 7;
    const float* wsrc = &g_Wh[((size_t)bh * Nc + jbase + sk) * Dc + snt * 8];
    int slot_w0 = (sk & 3) << 1;

    float acc[8][4] = {};
    float d0 = 0.f, d1 = 0.f;

    float4 vaN, vbN;
    {
        float4 va = *(const float4*)&wsrc[0];
        float4 vb = *(const float4*)&wsrc[4];
        float v[8] = {va.x, va.y, va.z, va.w, vb.x, vb.y, vb.z, vb.w};
        #pragma unroll
        for (int gc = 0; gc < 8; gc++)
            wsf[0][sk * 64 + ((gc ^ slot_w0) << 3) + snt] = __float_as_uint(v[gc]);
    }
    vaN = *(const float4*)&wsrc[(size_t)32 * Dc];
    vbN = *(const float4*)&wsrc[(size_t)32 * Dc + 4];
    uint32_t wA_c = bits0[0], wB_c = bits1[0];
    uint32_t wA_n = bits0[1], wB_n = bits1[1];
    __syncthreads();

    for (int t = 0; t < NTILE_H; t++){
        float4 va2 = make_float4(0,0,0,0), vb2 = va2;
        uint32_t wA2 = 0, wB2 = 0;
        if (t + 2 < NTILE_H){
            va2 = *(const float4*)&wsrc[(size_t)(t + 2) * 32 * Dc];
            vb2 = *(const float4*)&wsrc[(size_t)(t + 2) * 32 * Dc + 4];
            wA2 = bits0[t + 2]; wB2 = bits1[t + 2];
        }
        if (t + 1 < NTILE_H){
            float v[8] = {vaN.x, vaN.y, vaN.z, vaN.w, vbN.x, vbN.y, vbN.z, vbN.w};
            uint32_t* W = wsf[(t + 1) & 1];
            #pragma unroll
            for (int gc = 0; gc < 8; gc++)
                W[sk * 64 + ((gc ^ slot_w0) << 3) + snt] = __float_as_uint(v[gc]);
        }
        const uint32_t* W = wsf[t & 1];
        int slot_r = g ^ (tig << 1);
        #pragma unroll
        for (int ks = 0; ks < 4; ks++){
            int jb = t * 32 + ks * 8;
            float4 t0 = jtab[jb + tig];
            float4 t1 = jtab[jb + tig + 4];
            int sh = ks * 8 + tig;
            float p0 = (psil0 + t0.x > 0.f) ? pa10 * t0.y : pa20 * t0.z; if (!((wA_c >> sh) & 1))       p0 = 0.f;
            float p1 = (psil1 + t0.x > 0.f) ? pa11 * t0.y : pa21 * t0.z; if (!((wB_c >> sh) & 1))       p1 = 0.f;
            float p2 = (psil0 + t1.x > 0.f) ? pa10 * t1.y : pa20 * t1.z; if (!((wA_c >> (sh + 4)) & 1)) p2 = 0.f;
            float p3 = (psil1 + t1.x > 0.f) ? pa11 * t1.y : pa21 * t1.z; if (!((wB_c >> (sh + 4)) & 1)) p3 = 0.f;
            uint32_t a0 = tf32u(p0), a1 = tf32u(p1), a2 = tf32u(p2), a3 = tf32u(p3);
            d0 += __uint_as_float(a0) + __uint_as_float(a2);
            d1 += __uint_as_float(a1) + __uint_as_float(a3);
            const uint32_t* br0 = &W[ sh      * 64 + slot_r * 8];
            const uint32_t* br1 = &W[(sh + 4) * 64 + slot_r * 8];
            uint4 b00 = *(const uint4*)br0;
            uint4 b01 = *(const uint4*)(br0 + 4);
            uint4 b10 = *(const uint4*)br1;
            uint4 b11 = *(const uint4*)(br1 + 4);
            mma8(acc[0], a0, a1, a2, a3, b00.x, b10.x);
            mma8(acc[1], a0, a1, a2, a3, b00.y, b10.y);
            mma8(acc[2], a0, a1, a2, a3, b00.z, b10.z);
            mma8(acc[3], a0, a1, a2, a3, b00.w, b10.w);
            mma8(acc[4], a0, a1, a2, a3, b01.x, b11.x);
            mma8(acc[5], a0, a1, a2, a3, b01.y, b11.y);
            mma8(acc[6], a0, a1, a2, a3, b01.z, b11.z);
            mma8(acc[7], a0, a1, a2, a3, b01.w, b11.w);
        }
        vaN = va2; vbN = vb2;
        wA_c = wA_n; wB_c = wB_n; wA_n = wA2; wB_n = wB2;
        __syncthreads();
    }

    d0 += __shfl_xor_sync(0xffffffffu, d0, 1); d0 += __shfl_xor_sync(0xffffffffu, d0, 2);
    d1 += __shfl_xor_sync(0xffffffffu, d1, 1); d1 += __shfl_xor_sync(0xffffffffu, d1, 2);

    // ---- write partials (no normalization) ----
    int n = i0 + r0;
    if (tig == 0){
        g_pden[jh][(size_t)bh * Nc + n]     = d0;
        g_pden[jh][(size_t)bh * Nc + n + 8] = d1;
    }
    float* p0o = &g_part[jh][((size_t)bh * Nc + n    ) * Dc];
    float* p1o = &g_part[jh][((size_t)bh * Nc + n + 8) * Dc];
    #pragma unroll
    for (int nt = 0; nt < 8; nt++){
        *(float2*)&p0o[nt * 8 + 2 * tig] = make_float2(acc[nt][0], acc[nt][1]);
        *(float2*)&p1o[nt * 8 + 2 * tig] = make_float2(acc[nt][2], acc[nt][3]);
    }
}

// ---------------------------------------------------------------------------
// Combine: out = (O0 + O1) / (d0 + d1), optional ELU, concat layout write.
// One warp per output row (n of one bh); 8 rows per 256-thread block.
// ---------------------------------------------------------------------------
template<bool ELU, bool TO_GX>
__global__ __launch_bounds__(256) void combine_kernel(float* __restrict__ out_ext)
{
    int row = blockIdx.x * 8 + (threadIdx.x >> 5);   // (bh, n) flattened
    int lane = threadIdx.x & 31;
    int bh = row >> 10, n = row & (Nc - 1);
    float inv = 1.f / (g_pden[0][row] + g_pden[1][row]);
    const float* p0 = &g_part[0][(size_t)row * Dc];
    const float* p1 = &g_part[1][(size_t)row * Dc];
    int b = bh / Hc, hh = bh % Hc;
    float* op = (TO_GX ? (float*)g_x : out_ext) + (size_t)(b * Nc + n) * HIDc + hh * Dc;
    float2 u0 = *(const float2*)&p0[lane * 2];
    float2 u1 = *(const float2*)&p1[lane * 2];
    float v0 = (u0.x + u1.x) * inv;
    float v1 = (u0.y + u1.y) * inv;
    if (ELU){
        v0 = v0 > 0.f ? v0 : expm1f(v0);
        v1 = v1 > 0.f ? v1 : expm1f(v1);
    }
    *(float2*)&op[lane * 2] = make_float2(v0, v1);
}

// ---------------------------------------------------------------------------
extern "C" void kernel_launch(void* const* d_in, const int* in_sizes, int n_in,
                              void* d_out, int out_size)
{
    const float* h   = (const float*)d_in[0];
    const float* adj = (const float*)d_in[1];
    const float* W1  = (const float*)d_in[2];
    const float* a1  = (const float*)d_in[3];
    const float* W2  = (const float*)d_in[4];
    const float* a2  = (const float*)d_in[5];
    float* out = (float*)d_out;

    dim3 projGrid(Bc * Nc / 128, Hc);        // (64, 3)
    dim3 attnGrid(Nc / 128, BHc, JSPLIT);    // (8, 24, 2) = 384
    int combBlocks = BHc * Nc / 8;           // 3072

    adjbits_kernel<<<(Nc * 32 * 32) / 256, 256>>>(adj);
    proj_mma<OBSc, false><<<projGrid, 256>>>(h, W1, a1);
    attn_frag<<<attnGrid, 256>>>();
    combine_kernel<true, true><<<combBlocks, 256>>>(nullptr);
    proj_mma<HIDc, true ><<<projGrid, 256>>>(nullptr, W2, a2);
    attn_frag<<<attnGrid, 256>>>();
    combine_kernel<false, false><<<combBlocks, 256>>>(out);
}